// round 11
// baseline (speedup 1.0000x reference)
#include <cuda_runtime.h>

typedef unsigned long long ULL;

// Problem constants: B=8192, T=100, D=16, H=32, Hd=50
#define NB 8192
#define NT 100
#define ND 16
#define NH 32
#define NHD 50
#define NEUL 10

#define TPE 8                 // threads (roles) per element group
#define GPB 32                // groups per block (256 threads / 8)
#define E 2                   // elements per group
#define NTHREADS 256          // 8 warps -> 2 per SMSP on all 4 SMSPs
#define EPB (GPB*E)           // 64 elements per block
#define NBLOCKS (NB/EPB)      // 128 -> 1 block per SM

// Strides (floats). Weights: ==4 (mod 8) -> 8 roles hit distinct bank quads; 16B-aligned rows.
#define W1S 36                // W1 h-part: 56 rows x 32 cols
#define W2S 60                // W2: 32 rows x 56 cols (50 real + 6 zero)
#define W3S 36                // W3: 64 rows x 32 cols
// Activations: ==2 (mod 8); 8B-aligned LDS.64.
#define HS  34
#define Z1S 58

__device__ __forceinline__ ULL ffma2(ULL a, ULL b, ULL c) {
    ULL d;
    asm("fma.rn.f32x2 %0, %1, %2, %3;" : "=l"(d) : "l"(a), "l"(b), "l"(c));
    return d;
}
__device__ __forceinline__ float sum2(ULL v) {
    return __uint_as_float((unsigned)v) + __uint_as_float((unsigned)(v >> 32));
}

// Accurate tanh: ex2 + rcp MUFUs, abs err ~1e-7
__device__ __forceinline__ float fast_tanh(float v) {
    float ax = fabsf(v) * 2.8853900817779268f;   // 2*log2(e)
    float e;
    asm("ex2.approx.f32 %0, %1;" : "=f"(e) : "f"(ax));
    float r = 1.0f - __fdividef(2.0f, e + 1.0f);
    return copysignf(r, v);
}

__global__ __launch_bounds__(NTHREADS, 1) void latentode_kernel(
    const float* __restrict__ g_dt, const float* __restrict__ g_x,
    const float* __restrict__ g_W1, const float* __restrict__ g_b1,
    const float* __restrict__ g_W2, const float* __restrict__ g_b2,
    const float* __restrict__ g_W3, const float* __restrict__ g_b3,
    const float* __restrict__ g_W4, const float* __restrict__ g_b4,
    float* __restrict__ g_out)
{
    __shared__ float W1s[56 * W1S];      // 2016 fl : h-part (cols 16..47), rows padded to 56
    __shared__ float W2s[NH * W2S];      // 1920 fl
    __shared__ float W3s[2 * NH * W3S];  // 2304 fl
    __shared__ float hs [EPB * HS];      // 2176 fl
    __shared__ float z1s[EPB * Z1S];     // 3712 fl
    // total 12128 fl = 48512 B <= 49152 static limit

    const int tid = threadIdx.x;
    const int r   = tid & 7;              // role
    const int g   = tid >> 3;             // group in block
    const int elb = g * E;
    const int b0  = blockIdx.x * EPB + elb;

    // ---- stage weights (zero-padded) ----
    for (int i = tid; i < 56 * W1S; i += NTHREADS) {
        int row = i / W1S, col = i - row * W1S;
        W1s[i] = (row < NHD && col < NH) ? g_W1[row * (ND + NH) + ND + col] : 0.0f;
    }
    for (int i = tid; i < NH * W2S; i += NTHREADS) {
        int row = i / W2S, col = i - row * W2S;
        W2s[i] = (col < NHD) ? g_W2[row * NHD + col] : 0.0f;
    }
    for (int i = tid; i < 2 * NH * W3S; i += NTHREADS) {
        int row = i / W3S, col = i - row * W3S;
        W3s[i] = (col < NH) ? g_W3[row * NH + col] : 0.0f;
    }
    for (int i = tid; i < EPB * Z1S; i += NTHREADS) z1s[i] = 0.0f;
    for (int i = tid; i < EPB * HS;  i += NTHREADS) hs[i]  = 0.0f;

    // ---- per-thread constants ----
    float b1r[7];
#pragma unroll
    for (int j = 0; j < 7; j++) { int row = r + 8 * j; b1r[j] = (row < NHD) ? g_b1[row] : 0.0f; }
    float b2r[4], b3r[8], w4r[8];
#pragma unroll
    for (int j = 0; j < 4; j++) b2r[j] = g_b2[r + 8 * j];
#pragma unroll
    for (int j = 0; j < 8; j++) { b3r[j] = g_b3[r + 8 * j]; w4r[j] = g_W4[r + 8 * j]; }
    const float b4v = g_b4[0];

    float h_own[4][E];                    // this lane's h rows (r+8j) per element
#pragma unroll
    for (int j = 0; j < 4; j++)
#pragma unroll
        for (int e = 0; e < E; e++) h_own[j][e] = 0.0f;

    __syncthreads();

    const float* hb = hs  + elb * HS;
    const float* zb = z1s + elb * Z1S;

#pragma unroll 1
    for (int t = 0; t < NT; t++) {
        // ---- per-timestep precompute, element-at-a-time ----
        float sc[E], x0[E], p1[7][E];
#pragma unroll 1
        for (int e = 0; e < E; e++) {
            float2 dv = *(const float2*)(g_dt + ((size_t)(b0 + e)) * NT * 2 + (size_t)t * 2);
            sc[e] = (dv.y - dv.x) * (0.1f / 24.0f);   // STEP * DT_SCALER folded

            const float4* xv = (const float4*)(g_x + ((size_t)(b0 + e)) * NT * ND + (size_t)t * ND);
            float4 xa = xv[0], xb4 = xv[1], xc = xv[2], xd = xv[3];
            x0[e] = xa.x;
#pragma unroll
            for (int j = 0; j < 7; j++) {
                int row = r + 8 * j;
                if (row < NHD) {
                    const float4* wp = (const float4*)(g_W1 + row * (ND + NH));  // x-part, L1-hot
                    float4 w0 = wp[0], w1 = wp[1], w2 = wp[2], w3 = wp[3];
                    float acc = b1r[j];
                    acc = fmaf(w0.x, xa.x, acc);  acc = fmaf(w0.y, xa.y, acc);
                    acc = fmaf(w0.z, xa.z, acc);  acc = fmaf(w0.w, xa.w, acc);
                    acc = fmaf(w1.x, xb4.x, acc); acc = fmaf(w1.y, xb4.y, acc);
                    acc = fmaf(w1.z, xb4.z, acc); acc = fmaf(w1.w, xb4.w, acc);
                    acc = fmaf(w2.x, xc.x, acc);  acc = fmaf(w2.y, xc.y, acc);
                    acc = fmaf(w2.z, xc.z, acc);  acc = fmaf(w2.w, xc.w, acc);
                    acc = fmaf(w3.x, xd.x, acc);  acc = fmaf(w3.y, xd.y, acc);
                    acc = fmaf(w3.z, xd.z, acc);  acc = fmaf(w3.w, xd.w, acc);
                    p1[j][e] = acc;
                } else {
                    p1[j][e] = 0.0f;              // pad rows -> z1 = tanh(0) = 0
                }
            }
        }
        float dyacc[E];
#pragma unroll
        for (int e = 0; e < E; e++) dyacc[e] = 0.0f;

#pragma unroll 1
        for (int it = 0; it < NEUL; it++) {
            // ===== merged h-pass: one h load feeds W3 (8 rows) + W1h (7 rows), 30 chains =====
            // unroll 2: caps ptxas load-hoisting -> live set stays under the reg ceiling
            {
                ULL a3[8][E], a1[7][E];
#pragma unroll
                for (int j = 0; j < 8; j++)
#pragma unroll
                    for (int e = 0; e < E; e++) a3[j][e] = 0ULL;
#pragma unroll
                for (int j = 0; j < 7; j++)
#pragma unroll
                    for (int e = 0; e < E; e++) a1[j][e] = 0ULL;

                const float* w3 = W3s + r * W3S;
                const float* w1 = W1s + r * W1S;
#pragma unroll 2
                for (int kp = 0; kp < 8; kp++) {
                    ULL h0[E], h1[E];
#pragma unroll
                    for (int e = 0; e < E; e++) {
                        const ULL* p = (const ULL*)(hb + e * HS + 4 * kp);
                        h0[e] = p[0]; h1[e] = p[1];
                    }
#pragma unroll
                    for (int j = 0; j < 8; j++) {
                        ulonglong2 w = *(const ulonglong2*)(w3 + j * 8 * W3S + 4 * kp);
#pragma unroll
                        for (int e = 0; e < E; e++) {
                            a3[j][e] = ffma2(w.x, h0[e], a3[j][e]);
                            a3[j][e] = ffma2(w.y, h1[e], a3[j][e]);
                        }
                    }
#pragma unroll
                    for (int j = 0; j < 7; j++) {
                        ulonglong2 w = *(const ulonglong2*)(w1 + j * 8 * W1S + 4 * kp);
#pragma unroll
                        for (int e = 0; e < E; e++) {
                            a1[j][e] = ffma2(w.x, h0[e], a1[j][e]);
                            a1[j][e] = ffma2(w.y, h1[e], a1[j][e]);
                        }
                    }
                }
#pragma unroll
                for (int j = 0; j < 8; j++)
#pragma unroll
                    for (int e = 0; e < E; e++)
                        dyacc[e] = fmaf(w4r[j], fast_tanh(sum2(a3[j][e]) + b3r[j]), dyacc[e]);
#pragma unroll
                for (int j = 0; j < 7; j++)
#pragma unroll
                    for (int e = 0; e < E; e++)     // rows 50..55 write tanh(0)=0 into pad
                        z1s[(elb + e) * Z1S + r + 8 * j] = fast_tanh(sum2(a1[j][e]) + p1[j][e]);
            }
            __syncwarp();

            // ===== W2 path: h += sc * tanh(z1 @ W2^T + b2)  (4 rows) =====
            {
                ULL a[4][E];
#pragma unroll
                for (int jj = 0; jj < 4; jj++)
#pragma unroll
                    for (int e = 0; e < E; e++) a[jj][e] = 0ULL;
                const float* w2 = W2s + r * W2S;
#pragma unroll 2
                for (int kp = 0; kp < 14; kp++) {   // 56 cols; pads multiply by 0
                    ULL z0[E], z1v[E];
#pragma unroll
                    for (int e = 0; e < E; e++) {
                        const ULL* p = (const ULL*)(zb + e * Z1S + 4 * kp);
                        z0[e] = p[0]; z1v[e] = p[1];
                    }
#pragma unroll
                    for (int jj = 0; jj < 4; jj++) {
                        ulonglong2 w = *(const ulonglong2*)(w2 + jj * 8 * W2S + 4 * kp);
#pragma unroll
                        for (int e = 0; e < E; e++) {
                            a[jj][e] = ffma2(w.x, z0[e], a[jj][e]);
                            a[jj][e] = ffma2(w.y, z1v[e], a[jj][e]);
                        }
                    }
                }
#pragma unroll
                for (int jj = 0; jj < 4; jj++) {
                    int row = r + 8 * jj;
#pragma unroll
                    for (int e = 0; e < E; e++) {
                        h_own[jj][e] = fmaf(sc[e], fast_tanh(sum2(a[jj][e]) + b2r[jj]), h_own[jj][e]);
                        hs[(elb + e) * HS + row] = h_own[jj][e];
                    }
                }
            }
            __syncwarp();
        }

        // ---- once per timestep: reduce dyacc across the 8-lane group, emit y ----
#pragma unroll
        for (int e = 0; e < E; e++) {
            float red = dyacc[e];
            red += __shfl_xor_sync(0xffffffffu, red, 1);
            red += __shfl_xor_sync(0xffffffffu, red, 2);
            red += __shfl_xor_sync(0xffffffffu, red, 4);
            if (r == 0)
                g_out[((size_t)(b0 + e)) * NT + t] =
                    fmaf(sc[e], red + 10.0f * b4v, x0[e]);
        }
    }
}

extern "C" void kernel_launch(void* const* d_in, const int* in_sizes, int n_in,
                              void* d_out, int out_size) {
    latentode_kernel<<<NBLOCKS, NTHREADS>>>(
        (const float*)d_in[0],  // dt (8192,100,2)
        (const float*)d_in[1],  // x  (8192,100,16)
        (const float*)d_in[2],  // W1 (50,48)
        (const float*)d_in[3],  // b1 (50)
        (const float*)d_in[4],  // W2 (32,50)
        (const float*)d_in[5],  // b2 (32)
        (const float*)d_in[6],  // W3 (64,32)
        (const float*)d_in[7],  // b3 (64)
        (const float*)d_in[8],  // W4 (1,64)
        (const float*)d_in[9],  // b4 (1)
        (float*)d_out);         // out (8192,100) float32
}

// round 12
// speedup vs baseline: 1.1276x; 1.1276x over previous
#include <cuda_runtime.h>

typedef unsigned long long ULL;

// Problem constants: B=8192, T=100, D=16, H=32, Hd=50
#define NB 8192
#define NT 100
#define ND 16
#define NH 32
#define NHD 50
#define NEUL 10

#define TPE 8                 // threads (roles) per element group
#define GPB 32                // groups per block (256 threads / 8)
#define E 2                   // elements per group
#define NTHREADS 256          // 8 warps -> 2 per SMSP on all 4 SMSPs
#define EPB (GPB*E)           // 64 elements per block
#define NBLOCKS (NB/EPB)      // 128 -> 1 block per SM

// Strides (floats). Weights: ==4 (mod 8) -> 8 roles hit distinct bank quads; 16B-aligned rows.
#define W1S 36                // W1 h-part: 56 rows x 32 cols
#define W2S 52                // W2: 32 rows x 52 cols (50 real + 2 zero)
#define W3S 36                // W3: 64 rows x 32 cols
// Activations: ==2 (mod 8); 8B-aligned LDS.64.
#define HS  34
#define Z1S 58

__device__ __forceinline__ ULL ffma2(ULL a, ULL b, ULL c) {
    ULL d;
    asm("fma.rn.f32x2 %0, %1, %2, %3;" : "=l"(d) : "l"(a), "l"(b), "l"(c));
    return d;
}
__device__ __forceinline__ float sum2(ULL v) {
    return __uint_as_float((unsigned)v) + __uint_as_float((unsigned)(v >> 32));
}

// HW tanh (sm_75+): 1 MUFU, abs err ~5e-4 — error budget analyzed vs 1e-3 gate.
__device__ __forceinline__ float fast_tanh(float v) {
    float r;
    asm("tanh.approx.f32 %0, %1;" : "=f"(r) : "f"(v));
    return r;
}

__global__ __launch_bounds__(NTHREADS, 1) void latentode_kernel(
    const float* __restrict__ g_dt, const float* __restrict__ g_x,
    const float* __restrict__ g_W1, const float* __restrict__ g_b1,
    const float* __restrict__ g_W2, const float* __restrict__ g_b2,
    const float* __restrict__ g_W3, const float* __restrict__ g_b3,
    const float* __restrict__ g_W4, const float* __restrict__ g_b4,
    float* __restrict__ g_out)
{
    __shared__ float W1s[56 * W1S];      // 2016 fl : h-part (cols 16..47), rows padded to 56
    __shared__ float W2s[NH * W2S];      // 1664 fl
    __shared__ float W3s[2 * NH * W3S];  // 2304 fl
    __shared__ float hs [EPB * HS];      // 2176 fl
    __shared__ float z1s[EPB * Z1S];     // 3712 fl

    const int tid = threadIdx.x;
    const int r   = tid & 7;              // role
    const int g   = tid >> 3;             // group in block
    const int elb = g * E;
    const int b0  = blockIdx.x * EPB + elb;

    // ---- stage weights (zero-padded) ----
    for (int i = tid; i < 56 * W1S; i += NTHREADS) {
        int row = i / W1S, col = i - row * W1S;
        W1s[i] = (row < NHD && col < NH) ? g_W1[row * (ND + NH) + ND + col] : 0.0f;
    }
    for (int i = tid; i < NH * W2S; i += NTHREADS) {
        int row = i / W2S, col = i - row * W2S;
        W2s[i] = (col < NHD) ? g_W2[row * NHD + col] : 0.0f;   // cols 50,51 zero
    }
    for (int i = tid; i < 2 * NH * W3S; i += NTHREADS) {
        int row = i / W3S, col = i - row * W3S;
        W3s[i] = (col < NH) ? g_W3[row * NH + col] : 0.0f;
    }
    for (int i = tid; i < EPB * Z1S; i += NTHREADS) z1s[i] = 0.0f;
    for (int i = tid; i < EPB * HS;  i += NTHREADS) hs[i]  = 0.0f;

    // ---- per-thread constants ----
    float b1r[7];
#pragma unroll
    for (int j = 0; j < 7; j++) { int row = r + 8 * j; b1r[j] = (row < NHD) ? g_b1[row] : 0.0f; }
    float b2r[4], b3r[8], w4r[8];
#pragma unroll
    for (int j = 0; j < 4; j++) b2r[j] = g_b2[r + 8 * j];
#pragma unroll
    for (int j = 0; j < 8; j++) { b3r[j] = g_b3[r + 8 * j]; w4r[j] = g_W4[r + 8 * j]; }
    const float b4v = g_b4[0];

    float h_own[4][E];                    // this lane's h rows (r+8j) per element
#pragma unroll
    for (int j = 0; j < 4; j++)
#pragma unroll
        for (int e = 0; e < E; e++) h_own[j][e] = 0.0f;

    __syncthreads();

    const float* hb = hs  + elb * HS;
    const float* zb = z1s + elb * Z1S;

#pragma unroll 1
    for (int t = 0; t < NT; t++) {
        // ---- per-timestep precompute, element-at-a-time ----
        float sc[E], x0[E], p1[7][E];
#pragma unroll 1
        for (int e = 0; e < E; e++) {
            float2 dv = *(const float2*)(g_dt + ((size_t)(b0 + e)) * NT * 2 + (size_t)t * 2);
            sc[e] = (dv.y - dv.x) * (0.1f / 24.0f);   // STEP * DT_SCALER folded

            const float4* xv = (const float4*)(g_x + ((size_t)(b0 + e)) * NT * ND + (size_t)t * ND);
            float4 xa = xv[0], xb4 = xv[1], xc = xv[2], xd = xv[3];
            x0[e] = xa.x;
#pragma unroll
            for (int j = 0; j < 7; j++) {
                int row = r + 8 * j;
                if (row < NHD) {
                    const float4* wp = (const float4*)(g_W1 + row * (ND + NH));  // x-part, L1-hot
                    float4 w0 = wp[0], w1 = wp[1], w2 = wp[2], w3 = wp[3];
                    float acc = b1r[j];
                    acc = fmaf(w0.x, xa.x, acc);  acc = fmaf(w0.y, xa.y, acc);
                    acc = fmaf(w0.z, xa.z, acc);  acc = fmaf(w0.w, xa.w, acc);
                    acc = fmaf(w1.x, xb4.x, acc); acc = fmaf(w1.y, xb4.y, acc);
                    acc = fmaf(w1.z, xb4.z, acc); acc = fmaf(w1.w, xb4.w, acc);
                    acc = fmaf(w2.x, xc.x, acc);  acc = fmaf(w2.y, xc.y, acc);
                    acc = fmaf(w2.z, xc.z, acc);  acc = fmaf(w2.w, xc.w, acc);
                    acc = fmaf(w3.x, xd.x, acc);  acc = fmaf(w3.y, xd.y, acc);
                    acc = fmaf(w3.z, xd.z, acc);  acc = fmaf(w3.w, xd.w, acc);
                    p1[j][e] = acc;
                } else {
                    p1[j][e] = 0.0f;              // pad rows -> z1 = tanh(0) = 0
                }
            }
        }
        float dyacc[E];
#pragma unroll
        for (int e = 0; e < E; e++) dyacc[e] = 0.0f;

#pragma unroll 1
        for (int it = 0; it < NEUL; it++) {
            // ===== merged h-pass: one h load feeds W3 (8 rows) + W1h (7 rows), 30 chains =====
            {
                ULL a3[8][E], a1[7][E];
#pragma unroll
                for (int j = 0; j < 8; j++)
#pragma unroll
                    for (int e = 0; e < E; e++) a3[j][e] = 0ULL;
#pragma unroll
                for (int j = 0; j < 7; j++)
#pragma unroll
                    for (int e = 0; e < E; e++) a1[j][e] = 0ULL;

                const float* w3 = W3s + r * W3S;
                const float* w1 = W1s + r * W1S;
#pragma unroll
                for (int kp = 0; kp < 8; kp++) {
                    ULL h0[E], h1[E];
#pragma unroll
                    for (int e = 0; e < E; e++) {
                        const ULL* p = (const ULL*)(hb + e * HS + 4 * kp);
                        h0[e] = p[0]; h1[e] = p[1];
                    }
#pragma unroll
                    for (int j = 0; j < 8; j++) {
                        ulonglong2 w = *(const ulonglong2*)(w3 + j * 8 * W3S + 4 * kp);
#pragma unroll
                        for (int e = 0; e < E; e++) {
                            a3[j][e] = ffma2(w.x, h0[e], a3[j][e]);
                            a3[j][e] = ffma2(w.y, h1[e], a3[j][e]);
                        }
                    }
#pragma unroll
                    for (int j = 0; j < 7; j++) {
                        ulonglong2 w = *(const ulonglong2*)(w1 + j * 8 * W1S + 4 * kp);
#pragma unroll
                        for (int e = 0; e < E; e++) {
                            a1[j][e] = ffma2(w.x, h0[e], a1[j][e]);
                            a1[j][e] = ffma2(w.y, h1[e], a1[j][e]);
                        }
                    }
                }
#pragma unroll
                for (int j = 0; j < 8; j++)
#pragma unroll
                    for (int e = 0; e < E; e++)
                        dyacc[e] = fmaf(w4r[j], fast_tanh(sum2(a3[j][e]) + b3r[j]), dyacc[e]);
#pragma unroll
                for (int j = 0; j < 7; j++)
#pragma unroll
                    for (int e = 0; e < E; e++)     // rows 50..55 write tanh(0)=0 into pad
                        z1s[(elb + e) * Z1S + r + 8 * j] = fast_tanh(sum2(a1[j][e]) + p1[j][e]);
            }
            __syncwarp();

            // ===== W2 path: h += sc * tanh(z1 @ W2^T + b2)  (4 rows, 13 kp = 52 cols) =====
            {
                ULL a[4][E];
#pragma unroll
                for (int jj = 0; jj < 4; jj++)
#pragma unroll
                    for (int e = 0; e < E; e++) a[jj][e] = 0ULL;
                const float* w2 = W2s + r * W2S;
#pragma unroll
                for (int kp = 0; kp < 13; kp++) {   // 52 cols; cols 50,51 are zero pads
                    ULL z0[E], z1v[E];
#pragma unroll
                    for (int e = 0; e < E; e++) {
                        const ULL* p = (const ULL*)(zb + e * Z1S + 4 * kp);
                        z0[e] = p[0]; z1v[e] = p[1];
                    }
#pragma unroll
                    for (int jj = 0; jj < 4; jj++) {
                        ulonglong2 w = *(const ulonglong2*)(w2 + jj * 8 * W2S + 4 * kp);
#pragma unroll
                        for (int e = 0; e < E; e++) {
                            a[jj][e] = ffma2(w.x, z0[e], a[jj][e]);
                            a[jj][e] = ffma2(w.y, z1v[e], a[jj][e]);
                        }
                    }
                }
#pragma unroll
                for (int jj = 0; jj < 4; jj++) {
                    int row = r + 8 * jj;
#pragma unroll
                    for (int e = 0; e < E; e++) {
                        h_own[jj][e] = fmaf(sc[e], fast_tanh(sum2(a[jj][e]) + b2r[jj]), h_own[jj][e]);
                        hs[(elb + e) * HS + row] = h_own[jj][e];
                    }
                }
            }
            __syncwarp();
        }

        // ---- once per timestep: reduce dyacc across the 8-lane group, emit y ----
#pragma unroll
        for (int e = 0; e < E; e++) {
            float red = dyacc[e];
            red += __shfl_xor_sync(0xffffffffu, red, 1);
            red += __shfl_xor_sync(0xffffffffu, red, 2);
            red += __shfl_xor_sync(0xffffffffu, red, 4);
            if (r == 0)
                g_out[((size_t)(b0 + e)) * NT + t] =
                    fmaf(sc[e], red + 10.0f * b4v, x0[e]);
        }
    }
}

extern "C" void kernel_launch(void* const* d_in, const int* in_sizes, int n_in,
                              void* d_out, int out_size) {
    latentode_kernel<<<NBLOCKS, NTHREADS>>>(
        (const float*)d_in[0],  // dt (8192,100,2)
        (const float*)d_in[1],  // x  (8192,100,16)
        (const float*)d_in[2],  // W1 (50,48)
        (const float*)d_in[3],  // b1 (50)
        (const float*)d_in[4],  // W2 (32,50)
        (const float*)d_in[5],  // b2 (32)
        (const float*)d_in[6],  // W3 (64,32)
        (const float*)d_in[7],  // b3 (64)
        (const float*)d_in[8],  // W4 (1,64)
        (const float*)d_in[9],  // b4 (1)
        (float*)d_out);         // out (8192,100) float32
}